// round 4
// baseline (speedup 1.0000x reference)
#include <cuda_runtime.h>

// Problem constants
#define BATCH  4
#define SEQ    2048
#define DMODEL 1024
#define NHEAD  16
#define DHEAD  64
#define MTOT   (BATCH * SEQ)   // 8192 rows

// ---------------------------------------------------------------------------
// Scratch (no cudaMalloc allowed anywhere) — __device__ globals are the
// sanctioned workaround. 4 x 32MB fp32 buffers.
// ---------------------------------------------------------------------------
__device__ float g_q[(size_t)MTOT * DMODEL];
__device__ float g_k[(size_t)MTOT * DMODEL];
__device__ float g_v[(size_t)MTOT * DMODEL];
__device__ float g_ctx[(size_t)MTOT * DMODEL];

// ---------------------------------------------------------------------------
// GEMM: Y[M,N] = X[M,K] @ W[N,K]^T + bias[N]
// Both X and W are K-contiguous (NT gemm) -> coalesced loads for both.
// Tiles: 128x128xBK16, 256 threads, 8x8 micro-tile per thread.
// Smem stored transposed [k][row] so fragment loads are LDS.128.
// ---------------------------------------------------------------------------
#define GBM 128
#define GBN 128
#define GBK 16

__global__ __launch_bounds__(256)
void gemm_xwt(const float* __restrict__ X, const float* __restrict__ W,
              const float* __restrict__ bias, float* __restrict__ Y,
              int M, int N, int K)
{
    __shared__ float As[GBK][GBM + 4];   // [k][m], pad to kill STS conflicts
    __shared__ float Bs[GBK][GBN + 4];   // [k][n]

    const int tid = threadIdx.x;
    const int tx  = tid & 15;            // n-direction (8 cols each)
    const int ty  = tid >> 4;            // m-direction (8 rows each)
    const int bm  = blockIdx.y * GBM;
    const int bn  = blockIdx.x * GBN;

    float acc[8][8];
#pragma unroll
    for (int i = 0; i < 8; i++)
#pragma unroll
        for (int j = 0; j < 8; j++) acc[i][j] = 0.f;

    // Tile load mapping: 128x16 tile = 512 float4, 2 per thread.
    // element e: row = e>>2 (0..127), kcol = (e&3)*4 (0,4,8,12)
    const int r0 = tid >> 2;
    const int c0 = (tid & 3) * 4;
    const int r1 = r0 + 64;              // (tid+256)>>2
    const float* Xp0 = X + (size_t)(bm + r0) * K + c0;
    const float* Xp1 = X + (size_t)(bm + r1) * K + c0;
    const float* Wp0 = W + (size_t)(bn + r0) * K + c0;
    const float* Wp1 = W + (size_t)(bn + r1) * K + c0;

    for (int k0 = 0; k0 < K; k0 += GBK) {
        float4 xa0 = *(const float4*)(Xp0 + k0);
        float4 xa1 = *(const float4*)(Xp1 + k0);
        float4 wb0 = *(const float4*)(Wp0 + k0);
        float4 wb1 = *(const float4*)(Wp1 + k0);

        As[c0 + 0][r0] = xa0.x; As[c0 + 1][r0] = xa0.y;
        As[c0 + 2][r0] = xa0.z; As[c0 + 3][r0] = xa0.w;
        As[c0 + 0][r1] = xa1.x; As[c0 + 1][r1] = xa1.y;
        As[c0 + 2][r1] = xa1.z; As[c0 + 3][r1] = xa1.w;
        Bs[c0 + 0][r0] = wb0.x; Bs[c0 + 1][r0] = wb0.y;
        Bs[c0 + 2][r0] = wb0.z; Bs[c0 + 3][r0] = wb0.w;
        Bs[c0 + 0][r1] = wb1.x; Bs[c0 + 1][r1] = wb1.y;
        Bs[c0 + 2][r1] = wb1.z; Bs[c0 + 3][r1] = wb1.w;
        __syncthreads();

#pragma unroll
        for (int kk = 0; kk < GBK; kk++) {
            float4 a0 = *(const float4*)&As[kk][ty * 8];
            float4 a1 = *(const float4*)&As[kk][ty * 8 + 4];
            float4 b0 = *(const float4*)&Bs[kk][tx * 8];
            float4 b1 = *(const float4*)&Bs[kk][tx * 8 + 4];
            float a[8] = {a0.x, a0.y, a0.z, a0.w, a1.x, a1.y, a1.z, a1.w};
            float b[8] = {b0.x, b0.y, b0.z, b0.w, b1.x, b1.y, b1.z, b1.w};
#pragma unroll
            for (int i = 0; i < 8; i++)
#pragma unroll
                for (int j = 0; j < 8; j++)
                    acc[i][j] = fmaf(a[i], b[j], acc[i][j]);
        }
        __syncthreads();
    }

    float bv[8];
#pragma unroll
    for (int j = 0; j < 8; j++) bv[j] = bias[bn + tx * 8 + j];

#pragma unroll
    for (int i = 0; i < 8; i++) {
        float* yp = Y + (size_t)(bm + ty * 8 + i) * N + bn + tx * 8;
        float4 o0 = make_float4(acc[i][0] + bv[0], acc[i][1] + bv[1],
                                acc[i][2] + bv[2], acc[i][3] + bv[3]);
        float4 o1 = make_float4(acc[i][4] + bv[4], acc[i][5] + bv[5],
                                acc[i][6] + bv[6], acc[i][7] + bv[7]);
        *(float4*)yp       = o0;
        *(float4*)(yp + 4) = o1;
    }
}

// ---------------------------------------------------------------------------
// Flash attention (fp32, online softmax).
// Grid: (SEQ/64, NHEAD, BATCH). Block: 256 threads = 16(tx) x 16(ty),
// 4x4 micro-tile per thread over a 64x64 score tile.
// Smem: Qs^T [d][qrow] (pre-scaled by 1/8), KPs buffer reused:
//   phase A: K^T [d][kcol], phase B: P [qrow][kcol]. Vs natural [s][d].
// Static smem = 3 * 16KB = 48KB exactly (no dynamic-smem attribute needed).
// ---------------------------------------------------------------------------
__global__ __launch_bounds__(256)
void flash_attn(const float* __restrict__ Q, const float* __restrict__ K,
                const float* __restrict__ V, float* __restrict__ O)
{
    __shared__ float Qs[DHEAD * DHEAD];   // [d*64 + qrow]
    __shared__ float KPs[DHEAD * DHEAD];  // K^T then P
    __shared__ float Vs[DHEAD * DHEAD];   // [s*64 + d]

    const int tid = threadIdx.x;
    const int tx  = tid & 15;
    const int ty  = tid >> 4;
    const int qbase = blockIdx.x * 64;
    const int h     = blockIdx.y;
    const int b     = blockIdx.z;
    const size_t base = (size_t)b * SEQ * DMODEL + (size_t)h * DHEAD;

    // Load Q tile transposed + pre-scaled by 1/sqrt(DHEAD) = 1/8
#pragma unroll
    for (int r = 0; r < 4; r++) {
        int e  = tid + 256 * r;
        int s  = e >> 4;
        int d4 = (e & 15) * 4;
        float4 qv = *(const float4*)(Q + base + (size_t)(qbase + s) * DMODEL + d4);
        Qs[(d4 + 0) * 64 + s] = qv.x * 0.125f;
        Qs[(d4 + 1) * 64 + s] = qv.y * 0.125f;
        Qs[(d4 + 2) * 64 + s] = qv.z * 0.125f;
        Qs[(d4 + 3) * 64 + s] = qv.w * 0.125f;
    }

    float m[4], l[4], o[4][4];
#pragma unroll
    for (int i = 0; i < 4; i++) {
        m[i] = -1e30f; l[i] = 0.f;
#pragma unroll
        for (int j = 0; j < 4; j++) o[i][j] = 0.f;
    }

    for (int kt = 0; kt < SEQ / 64; kt++) {
        __syncthreads();   // prior-iter P/V consumers done (also orders Qs fill)

        // Load K tile transposed + V tile natural
#pragma unroll
        for (int r = 0; r < 4; r++) {
            int e  = tid + 256 * r;
            int s  = e >> 4;
            int d4 = (e & 15) * 4;
            size_t goff = base + (size_t)(kt * 64 + s) * DMODEL + d4;
            float4 kv = *(const float4*)(K + goff);
            KPs[(d4 + 0) * 64 + s] = kv.x;
            KPs[(d4 + 1) * 64 + s] = kv.y;
            KPs[(d4 + 2) * 64 + s] = kv.z;
            KPs[(d4 + 3) * 64 + s] = kv.w;
            *(float4*)&Vs[s * 64 + d4] = *(const float4*)(V + goff);
        }
        __syncthreads();

        // S = (Q/8) @ K^T   (64x64 tile, outer-product over d)
        float sc[4][4];
#pragma unroll
        for (int i = 0; i < 4; i++)
#pragma unroll
            for (int j = 0; j < 4; j++) sc[i][j] = 0.f;

#pragma unroll 16
        for (int d = 0; d < 64; d++) {
            float4 qa = *(const float4*)&Qs[d * 64 + ty * 4];
            float4 kb = *(const float4*)&KPs[d * 64 + tx * 4];
            float a[4]  = {qa.x, qa.y, qa.z, qa.w};
            float bb[4] = {kb.x, kb.y, kb.z, kb.w};
#pragma unroll
            for (int i = 0; i < 4; i++)
#pragma unroll
                for (int j = 0; j < 4; j++)
                    sc[i][j] = fmaf(a[i], bb[j], sc[i][j]);
        }

        // Online softmax. Row r = qbase + ty*4 + i owned by the 16 tx-lanes
        // of this ty; xor-shuffles with offsets 1..8 stay within the 16-lane
        // half-warp (same ty), so reductions are per-row.
#pragma unroll
        for (int i = 0; i < 4; i++) {
            float rm = fmaxf(fmaxf(sc[i][0], sc[i][1]), fmaxf(sc[i][2], sc[i][3]));
#pragma unroll
            for (int off = 1; off < 16; off <<= 1)
                rm = fmaxf(rm, __shfl_xor_sync(0xffffffffu, rm, off));
            float mn   = fmaxf(m[i], rm);
            float corr = __expf(m[i] - mn);
            float rs   = 0.f;
#pragma unroll
            for (int j = 0; j < 4; j++) {
                float p = __expf(sc[i][j] - mn);
                sc[i][j] = p;
                rs += p;
            }
#pragma unroll
            for (int off = 1; off < 16; off <<= 1)
                rs += __shfl_xor_sync(0xffffffffu, rs, off);
            l[i] = l[i] * corr + rs;
            m[i] = mn;
#pragma unroll
            for (int j = 0; j < 4; j++) o[i][j] *= corr;
        }

        __syncthreads();   // all done reading K^T before overwriting with P

        // Write P [qrow][kcol] into the K^T buffer
#pragma unroll
        for (int i = 0; i < 4; i++)
            *(float4*)&KPs[(ty * 4 + i) * 64 + tx * 4] =
                make_float4(sc[i][0], sc[i][1], sc[i][2], sc[i][3]);
        __syncthreads();

        // O += P @ V
#pragma unroll 16
        for (int kk = 0; kk < 64; kk++) {
            float4 vb = *(const float4*)&Vs[kk * 64 + tx * 4];
#pragma unroll
            for (int i = 0; i < 4; i++) {
                float pa = KPs[(ty * 4 + i) * 64 + kk];  // broadcast across tx
                o[i][0] = fmaf(pa, vb.x, o[i][0]);
                o[i][1] = fmaf(pa, vb.y, o[i][1]);
                o[i][2] = fmaf(pa, vb.z, o[i][2]);
                o[i][3] = fmaf(pa, vb.w, o[i][3]);
            }
        }
    }

    // Normalize and write context directly in merged [B,S,D] layout
#pragma unroll
    for (int i = 0; i < 4; i++) {
        float inv = 1.0f / l[i];
        float* op = O + base + (size_t)(qbase + ty * 4 + i) * DMODEL + tx * 4;
        *(float4*)op = make_float4(o[i][0] * inv, o[i][1] * inv,
                                   o[i][2] * inv, o[i][3] * inv);
    }
}

// ---------------------------------------------------------------------------
// Launch: 3 projections -> flash attention -> dense. All async on default
// stream, graph-capturable, zero device allocation, no statics/caching.
// Input order (metadata): v, k, q, wq_w, wq_b, wk_w, wk_b, wv_w, wv_b,
//                         dense_w, dense_b
// ---------------------------------------------------------------------------
extern "C" void kernel_launch(void* const* d_in, const int* in_sizes, int n_in,
                              void* d_out, int out_size)
{
    const float* v    = (const float*)d_in[0];
    const float* k    = (const float*)d_in[1];
    const float* q    = (const float*)d_in[2];
    const float* wq_w = (const float*)d_in[3];
    const float* wq_b = (const float*)d_in[4];
    const float* wk_w = (const float*)d_in[5];
    const float* wk_b = (const float*)d_in[6];
    const float* wv_w = (const float*)d_in[7];
    const float* wv_b = (const float*)d_in[8];
    const float* dw   = (const float*)d_in[9];
    const float* db   = (const float*)d_in[10];

    float *gq, *gk, *gv, *gctx;
    cudaGetSymbolAddress((void**)&gq,   g_q);
    cudaGetSymbolAddress((void**)&gk,   g_k);
    cudaGetSymbolAddress((void**)&gv,   g_v);
    cudaGetSymbolAddress((void**)&gctx, g_ctx);

    dim3 gt(DMODEL / GBN, MTOT / GBM);
    dim3 bt(256);

    gemm_xwt<<<gt, bt>>>(q, wq_w, wq_b, gq, MTOT, DMODEL, DMODEL);
    gemm_xwt<<<gt, bt>>>(k, wk_w, wk_b, gk, MTOT, DMODEL, DMODEL);
    gemm_xwt<<<gt, bt>>>(v, wv_w, wv_b, gv, MTOT, DMODEL, DMODEL);

    dim3 ga(SEQ / 64, NHEAD, BATCH);
    flash_attn<<<ga, bt>>>(gq, gk, gv, gctx);

    gemm_xwt<<<gt, bt>>>(gctx, dw, db, (float*)d_out, MTOT, DMODEL, DMODEL);
}

// round 8
// speedup vs baseline: 1.5453x; 1.5453x over previous
#include <cuda_runtime.h>
#include <cuda_bf16.h>
#include <cstdint>

// Problem constants
#define BATCH  4
#define SEQ    2048
#define DMODEL 1024
#define NHEAD  16
#define DHEAD  64
#define MTOT   (BATCH * SEQ)   // 8192 rows
#define KDIM   DMODEL

// ---------------------------------------------------------------------------
// Scratch (__device__ globals — the sanctioned no-alloc path)
// ---------------------------------------------------------------------------
__device__ float g_q[(size_t)MTOT * DMODEL];
__device__ float g_k[(size_t)MTOT * DMODEL];
__device__ float g_v[(size_t)MTOT * DMODEL];
__device__ float g_ctx[(size_t)MTOT * DMODEL];

// ---------------------------------------------------------------------------
// Helpers (baseline compute_103 PTX only — NO tcgen05/TMEM, those are
// sm_103a-gated and this harness emits .target sm_103)
// ---------------------------------------------------------------------------
__device__ __forceinline__ uint32_t smem_u32(const void* p) {
    uint32_t a;
    asm("{ .reg .u64 t; cvta.to.shared.u64 t, %1; cvt.u32.u64 %0, t; }"
        : "=r"(a) : "l"(p));
    return a;
}
__device__ __forceinline__ void ldsm4(uint32_t* r, uint32_t addr) {
    asm volatile("ldmatrix.sync.aligned.m8n8.x4.shared.b16 {%0,%1,%2,%3}, [%4];"
                 : "=r"(r[0]), "=r"(r[1]), "=r"(r[2]), "=r"(r[3]) : "r"(addr));
}
__device__ __forceinline__ void mma16816(float* d, const uint32_t* a, const uint32_t* b) {
    asm volatile(
        "mma.sync.aligned.m16n8k16.row.col.f32.bf16.bf16.f32 "
        "{%0,%1,%2,%3}, {%4,%5,%6,%7}, {%8,%9}, {%0,%1,%2,%3};"
        : "+f"(d[0]), "+f"(d[1]), "+f"(d[2]), "+f"(d[3])
        : "r"(a[0]), "r"(a[1]), "r"(a[2]), "r"(a[3]), "r"(b[0]), "r"(b[1]));
}
__device__ __forceinline__ uint32_t pack_bf2(__nv_bfloat16 a, __nv_bfloat16 b) {
    __nv_bfloat162 t = __halves2bfloat162(a, b);
    return *(uint32_t*)&t;
}

// ---------------------------------------------------------------------------
// GEMM via mma.sync bf16 3-term split:  Y[M,N] = X[M,K] @ W[N,K]^T + bias
//   x = hi + lo (both bf16); X·Wᵀ ≈ XhiWhi + XhiWlo + XloWhi (fp32 accum)
// fp32→(hi,lo) conversion fused into the smem loader (no split kernels).
//
// CTA: 128x128 tile, 256 thr (8 warps as 4(m) x 2(n)), warp tile 32x64,
// BK=32 per chunk (2 ksteps of 16). Register prefetch of next chunk hides
// LDG latency under the MMA phase (single 48KB static smem buffer).
//
// Smem k-slab layout per term: slab s(0/1) holds 128 rows x 16 bf16, row
// stride 48B -> ldmatrix phase addresses r*48 mod 128 all distinct
// (conflict-free LDSM). Terms: Ahi @0, Alo @12288, Bhi @24576, Blo @36864.
// ---------------------------------------------------------------------------
__global__ __launch_bounds__(256)
void gemm_mma(const float* __restrict__ X, const float* __restrict__ W,
              const float* __restrict__ bias, float* __restrict__ Y)
{
    __shared__ __align__(16) char smem[49152];
    const uint32_t sb = smem_u32(smem);

    const int tid  = threadIdx.x;
    const int lane = tid & 31, wid = tid >> 5;
    const int wm = wid & 3;        // 0..3 -> rows wm*32
    const int wn = wid >> 2;       // 0..1 -> cols wn*64
    const int bm = blockIdx.y * 128, bn = blockIdx.x * 128;

    // Loader mapping: thread t -> row lr (0..127), kstep slab ls (0/1);
    // covers 16 consecutive k per thread.
    const int lr = tid >> 1;
    const int ls = tid & 1;
    const float* Xp = X + (size_t)(bm + lr) * KDIM + ls * 16;
    const float* Wp = W + (size_t)(bn + lr) * KDIM + ls * 16;

    // ldmatrix per-lane address patterns
    // A (m16k16): lanes 0-7 rows r0..7 col0 | 8-15 rows+8 col0 | 16-23 rows col+16B | 24-31 rows+8 col+16B
    const uint32_t a_off = ((lane & 7) + ((lane >> 3) & 1) * 8) * 48 + ((lane >> 4) & 1) * 16;
    // B (k16n8 pair): lanes 0-7 n0..7 k0 | 8-15 n0..7 k8 | 16-23 n+8 k0 | 24-31 n+8 k8
    const uint32_t b_off = ((lane & 7) + ((lane >> 4) & 1) * 8) * 48 + ((lane >> 3) & 1) * 16;

    float acc[2][8][4];
#pragma unroll
    for (int mt = 0; mt < 2; mt++)
#pragma unroll
        for (int nt = 0; nt < 8; nt++)
#pragma unroll
            for (int e = 0; e < 4; e++) acc[mt][nt][e] = 0.f;

    // Prefetch chunk 0
    float4 ax[4], bx[4];
#pragma unroll
    for (int j = 0; j < 4; j++) {
        ax[j] = *(const float4*)(Xp + j * 4);
        bx[j] = *(const float4*)(Wp + j * 4);
    }

    const uint32_t dstA = sb + ls * 6144 + lr * 48;
    const uint32_t dstB = dstA + 24576;

    for (int c = 0; c < KDIM / 32; c++) {
        __syncthreads();   // previous compute done reading smem

        // Convert prefetched fp32 -> hi/lo bf16, store to smem k-slabs
        {
            uint32_t hA[8], lA[8], hB[8], lB[8];
#pragma unroll
            for (int j = 0; j < 4; j++) {
                float va[4] = {ax[j].x, ax[j].y, ax[j].z, ax[j].w};
                float vb[4] = {bx[j].x, bx[j].y, bx[j].z, bx[j].w};
#pragma unroll
                for (int p = 0; p < 2; p++) {
                    __nv_bfloat16 h0 = __float2bfloat16_rn(va[p*2]);
                    __nv_bfloat16 h1 = __float2bfloat16_rn(va[p*2+1]);
                    hA[j*2+p] = pack_bf2(h0, h1);
                    lA[j*2+p] = pack_bf2(
                        __float2bfloat16_rn(va[p*2]   - __bfloat162float(h0)),
                        __float2bfloat16_rn(va[p*2+1] - __bfloat162float(h1)));
                    __nv_bfloat16 g0 = __float2bfloat16_rn(vb[p*2]);
                    __nv_bfloat16 g1 = __float2bfloat16_rn(vb[p*2+1]);
                    hB[j*2+p] = pack_bf2(g0, g1);
                    lB[j*2+p] = pack_bf2(
                        __float2bfloat16_rn(vb[p*2]   - __bfloat162float(g0)),
                        __float2bfloat16_rn(vb[p*2+1] - __bfloat162float(g1)));
                }
            }
            char* cA = smem + (dstA - sb);
            char* cB = smem + (dstB - sb);
            *(uint4*)(cA)              = make_uint4(hA[0], hA[1], hA[2], hA[3]);
            *(uint4*)(cA + 16)         = make_uint4(hA[4], hA[5], hA[6], hA[7]);
            *(uint4*)(cA + 12288)      = make_uint4(lA[0], lA[1], lA[2], lA[3]);
            *(uint4*)(cA + 12288 + 16) = make_uint4(lA[4], lA[5], lA[6], lA[7]);
            *(uint4*)(cB)              = make_uint4(hB[0], hB[1], hB[2], hB[3]);
            *(uint4*)(cB + 16)         = make_uint4(hB[4], hB[5], hB[6], hB[7]);
            *(uint4*)(cB + 12288)      = make_uint4(lB[0], lB[1], lB[2], lB[3]);
            *(uint4*)(cB + 12288 + 16) = make_uint4(lB[4], lB[5], lB[6], lB[7]);
        }
        __syncthreads();

        // Issue next chunk's LDGs early (latency hides under MMA phase)
        if (c + 1 < KDIM / 32) {
            const float* xn = Xp + (c + 1) * 32;
            const float* wn_ = Wp + (c + 1) * 32;
#pragma unroll
            for (int j = 0; j < 4; j++) {
                ax[j] = *(const float4*)(xn + j * 4);
                bx[j] = *(const float4*)(wn_ + j * 4);
            }
        }

        // Compute: 2 ksteps x (16 mma x 3 terms)
#pragma unroll
        for (int s = 0; s < 2; s++) {
            const uint32_t slab = sb + s * 6144;
            uint32_t aH[2][4], aL[2][4], bH[4][4], bL[4][4];
#pragma unroll
            for (int mt = 0; mt < 2; mt++) {
                uint32_t ad = slab + (uint32_t)(wm * 32 + mt * 16) * 48 + a_off;
                ldsm4(aH[mt], ad);
                ldsm4(aL[mt], ad + 12288);
            }
#pragma unroll
            for (int p = 0; p < 4; p++) {
                uint32_t bd = slab + 24576 + (uint32_t)(wn * 64 + p * 16) * 48 + b_off;
                ldsm4(bH[p], bd);
                ldsm4(bL[p], bd + 12288);
            }
#pragma unroll
            for (int mt = 0; mt < 2; mt++)
#pragma unroll
                for (int p = 0; p < 4; p++)
#pragma unroll
                    for (int hlf = 0; hlf < 2; hlf++) {
                        const int nt = p * 2 + hlf;
                        mma16816(acc[mt][nt], aH[mt], &bH[p][hlf * 2]);
                        mma16816(acc[mt][nt], aH[mt], &bL[p][hlf * 2]);
                        mma16816(acc[mt][nt], aL[mt], &bH[p][hlf * 2]);
                    }
        }
    }

    // Epilogue: D fragment mapping — lane holds rows (l>>2, +8), cols (l&3)*2,+1
    const int er = bm + wm * 32 + (lane >> 2);
    const int ec = bn + wn * 64 + (lane & 3) * 2;
#pragma unroll
    for (int mt = 0; mt < 2; mt++)
#pragma unroll
        for (int nt = 0; nt < 8; nt++) {
            int row = er + mt * 16;
            int col = ec + nt * 8;
            float2 bv = *(const float2*)(bias + col);
            *(float2*)(Y + (size_t)row * DMODEL + col) =
                make_float2(acc[mt][nt][0] + bv.x, acc[mt][nt][1] + bv.y);
            *(float2*)(Y + (size_t)(row + 8) * DMODEL + col) =
                make_float2(acc[mt][nt][2] + bv.x, acc[mt][nt][3] + bv.y);
        }
}

// ---------------------------------------------------------------------------
// Flash attention v2 (fp32, online softmax), L1-crossbar optimized:
//   q-tile 128, k-tile 64, 256 threads = 16(tx: 4 cols) x 16(ty: 8 rows),
//   8x4 micro-tile (32 FMA / 48B LDS), padded smem strides (Qs 132, K^T 68)
//   to kill transposed-store bank conflicts.
// ---------------------------------------------------------------------------
#define QS_STRIDE 132
#define KT_STRIDE 68
#define FLASH_SMEM ((64 * QS_STRIDE + 128 * 64 + 64 * 64) * 4)

__global__ __launch_bounds__(256, 2)
void flash2(const float* __restrict__ Q, const float* __restrict__ K,
            const float* __restrict__ V, float* __restrict__ O)
{
    extern __shared__ float fs[];
    float* Qs  = fs;                          // [d][qrow], stride 132
    float* KPs = fs + 64 * QS_STRIDE;         // K^T [d][kcol] stride 68, then P [row][64]
    float* Vs  = KPs + 128 * 64;              // [s][d], stride 64

    const int tid = threadIdx.x;
    const int tx  = tid & 15;                 // 4 cols each (64 total)
    const int ty  = tid >> 4;                 // 8 rows each (128 total)
    const int qbase = blockIdx.x * 128;
    const int h     = blockIdx.y;
    const int b     = blockIdx.z;
    const size_t base = (size_t)b * SEQ * DMODEL + (size_t)h * DHEAD;

    // Load Q tile transposed + pre-scaled by 1/sqrt(64) = 0.125
#pragma unroll
    for (int r = 0; r < 8; r++) {
        int e  = tid + 256 * r;
        int s  = e >> 4;            // 0..127
        int d4 = (e & 15) * 4;      // 0..60
        float4 qv = *(const float4*)(Q + base + (size_t)(qbase + s) * DMODEL + d4);
        Qs[(d4 + 0) * QS_STRIDE + s] = qv.x * 0.125f;
        Qs[(d4 + 1) * QS_STRIDE + s] = qv.y * 0.125f;
        Qs[(d4 + 2) * QS_STRIDE + s] = qv.z * 0.125f;
        Qs[(d4 + 3) * QS_STRIDE + s] = qv.w * 0.125f;
    }

    float m[8], l[8], o[8][4];
#pragma unroll
    for (int i = 0; i < 8; i++) {
        m[i] = -1e30f; l[i] = 0.f;
#pragma unroll
        for (int j = 0; j < 4; j++) o[i][j] = 0.f;
    }

    for (int kt = 0; kt < SEQ / 64; kt++) {
        __syncthreads();  // prior-iter P/V consumers done (also orders Qs fill)

        // Load K tile transposed (stride 68) + V tile natural
#pragma unroll
        for (int r = 0; r < 4; r++) {
            int e  = tid + 256 * r;
            int s  = e >> 4;          // 0..63
            int d4 = (e & 15) * 4;
            size_t goff = base + (size_t)(kt * 64 + s) * DMODEL + d4;
            float4 kv = *(const float4*)(K + goff);
            KPs[(d4 + 0) * KT_STRIDE + s] = kv.x;
            KPs[(d4 + 1) * KT_STRIDE + s] = kv.y;
            KPs[(d4 + 2) * KT_STRIDE + s] = kv.z;
            KPs[(d4 + 3) * KT_STRIDE + s] = kv.w;
            *(float4*)&Vs[s * 64 + d4] = *(const float4*)(V + goff);
        }
        __syncthreads();

        // S = (Q/8) @ K^T  (128x64 tile, outer product over d)
        float sc[8][4];
#pragma unroll
        for (int i = 0; i < 8; i++)
#pragma unroll
            for (int j = 0; j < 4; j++) sc[i][j] = 0.f;

#pragma unroll 8
        for (int d = 0; d < 64; d++) {
            float4 qa0 = *(const float4*)&Qs[d * QS_STRIDE + ty * 8];
            float4 qa1 = *(const float4*)&Qs[d * QS_STRIDE + ty * 8 + 4];
            float4 kb  = *(const float4*)&KPs[d * KT_STRIDE + tx * 4];
            float a[8]  = {qa0.x, qa0.y, qa0.z, qa0.w, qa1.x, qa1.y, qa1.z, qa1.w};
            float bb[4] = {kb.x, kb.y, kb.z, kb.w};
#pragma unroll
            for (int i = 0; i < 8; i++)
#pragma unroll
                for (int j = 0; j < 4; j++)
                    sc[i][j] = fmaf(a[i], bb[j], sc[i][j]);
        }

        // Online softmax: row owned by the 16 tx-lanes of this ty group;
        // xor-shuffles 1..8 stay inside the 16-lane group.
#pragma unroll
        for (int i = 0; i < 8; i++) {
            float rm = fmaxf(fmaxf(sc[i][0], sc[i][1]), fmaxf(sc[i][2], sc[i][3]));
#pragma unroll
            for (int off = 1; off < 16; off <<= 1)
                rm = fmaxf(rm, __shfl_xor_sync(0xffffffffu, rm, off));
            float mn   = fmaxf(m[i], rm);
            float corr = __expf(m[i] - mn);
            float rs   = 0.f;
#pragma unroll
            for (int j = 0; j < 4; j++) {
                float p = __expf(sc[i][j] - mn);
                sc[i][j] = p;
                rs += p;
            }
#pragma unroll
            for (int off = 1; off < 16; off <<= 1)
                rs += __shfl_xor_sync(0xffffffffu, rs, off);
            l[i] = l[i] * corr + rs;
            m[i] = mn;
#pragma unroll
            for (int j = 0; j < 4; j++) o[i][j] *= corr;
        }

        __syncthreads();  // all reads of K^T done before overwriting with P

        // P [qrow][kcol], stride 64
#pragma unroll
        for (int i = 0; i < 8; i++)
            *(float4*)&KPs[(ty * 8 + i) * 64 + tx * 4] =
                make_float4(sc[i][0], sc[i][1], sc[i][2], sc[i][3]);
        __syncthreads();

        // O += P @ V
#pragma unroll 8
        for (int kk = 0; kk < 64; kk++) {
            float4 vb = *(const float4*)&Vs[kk * 64 + tx * 4];
#pragma unroll
            for (int i = 0; i < 8; i++) {
                float pa = KPs[(ty * 8 + i) * 64 + kk];   // broadcast across tx
                o[i][0] = fmaf(pa, vb.x, o[i][0]);
                o[i][1] = fmaf(pa, vb.y, o[i][1]);
                o[i][2] = fmaf(pa, vb.z, o[i][2]);
                o[i][3] = fmaf(pa, vb.w, o[i][3]);
            }
        }
    }

    // Normalize and write context in merged [B,S,D] layout
#pragma unroll
    for (int i = 0; i < 8; i++) {
        float inv = 1.0f / l[i];
        float* op = O + base + (size_t)(qbase + ty * 8 + i) * DMODEL + tx * 4;
        *(float4*)op = make_float4(o[i][0] * inv, o[i][1] * inv,
                                   o[i][2] * inv, o[i][3] * inv);
    }
}

// ---------------------------------------------------------------------------
// Launch. Input order: v, k, q, wq_w, wq_b, wk_w, wk_b, wv_w, wv_b,
//                      dense_w, dense_b
// ---------------------------------------------------------------------------
extern "C" void kernel_launch(void* const* d_in, const int* in_sizes, int n_in,
                              void* d_out, int out_size)
{
    const float* v    = (const float*)d_in[0];
    const float* k    = (const float*)d_in[1];
    const float* q    = (const float*)d_in[2];
    const float* wq_w = (const float*)d_in[3];
    const float* wq_b = (const float*)d_in[4];
    const float* wk_w = (const float*)d_in[5];
    const float* wk_b = (const float*)d_in[6];
    const float* wv_w = (const float*)d_in[7];
    const float* wv_b = (const float*)d_in[8];
    const float* dw   = (const float*)d_in[9];
    const float* db   = (const float*)d_in[10];

    float *gq, *gk, *gv, *gctx;
    cudaGetSymbolAddress((void**)&gq,   g_q);
    cudaGetSymbolAddress((void**)&gk,   g_k);
    cudaGetSymbolAddress((void**)&gv,   g_v);
    cudaGetSymbolAddress((void**)&gctx, g_ctx);

    cudaFuncSetAttribute(flash2, cudaFuncAttributeMaxDynamicSharedMemorySize, FLASH_SMEM);

    dim3 gg(DMODEL / 128, MTOT / 128);   // (8, 64)
    dim3 bt(256);

    gemm_mma<<<gg, bt>>>(q, wq_w, wq_b, gq);
    gemm_mma<<<gg, bt>>>(k, wk_w, wk_b, gk);
    gemm_mma<<<gg, bt>>>(v, wv_w, wv_b, gv);

    dim3 ga(SEQ / 128, NHEAD, BATCH);
    flash2<<<ga, bt, FLASH_SMEM>>>(gq, gk, gv, gctx);

    gemm_mma<<<gg, bt>>>(gctx, dw, db, (float*)d_out);
}